// round 14
// baseline (speedup 1.0000x reference)
#include <cuda_runtime.h>
#include <cuda_fp16.h>
#include <math.h>
#include <stdint.h>

#define BB    32
#define CINC  128
#define HH    64
#define WW    64
#define COUTC 128
#define NK    4
#define HIDN  32
#define TEMPF 34.0f

// halo-padded channel-last input: [B][66][66][CIN] fp16
#define HP 66
__device__ __half g_x[(size_t)BB*HP*HP*CINC];
// aggregated weights: [B][9][COUT][CIN] fp16
__device__ __half g_w[(size_t)BB*9*COUTC*CINC];
__device__ float g_part[(size_t)BB*CINC*128];   // mean partials: [b][ci][y*2+xhalf]
__device__ float g_att[BB*NK];
__device__ float g_aggb[BB*COUTC];
__device__ unsigned g_tilectr;                  // dynamic tile counter (reset in prepx)

// ---------------- PTX helpers ----------------
__device__ __forceinline__ uint32_t smem_u32(const void* p) {
    uint32_t a;
    asm("{ .reg .u64 t; cvta.to.shared.u64 t, %1; cvt.u32.u64 %0, t; }" : "=r"(a) : "l"(p));
    return a;
}
#define SW128(off) ((off) ^ (((off) >> 3) & 0x70))

__device__ __forceinline__ void cp16(uint32_t dst, const void* src) {
    asm volatile("cp.async.cg.shared.global [%0], [%1], 16;" :: "r"(dst), "l"(src));
}
#define CP_COMMIT() asm volatile("cp.async.commit_group;" ::: "memory")
#define CP_WAIT0()  asm volatile("cp.async.wait_group 0;" ::: "memory")

__device__ __forceinline__ void ldmx4(uint32_t* r, uint32_t addr) {
    asm volatile("ldmatrix.sync.aligned.m8n8.x4.shared.b16 {%0,%1,%2,%3}, [%4];"
                 : "=r"(r[0]), "=r"(r[1]), "=r"(r[2]), "=r"(r[3]) : "r"(addr));
}
__device__ __forceinline__ void mma_f16(float* d, const uint32_t* a, const uint32_t* b) {
    asm volatile("mma.sync.aligned.m16n8k16.row.col.f32.f16.f16.f32 "
                 "{%0,%1,%2,%3}, {%4,%5,%6,%7}, {%8,%9}, {%0,%1,%2,%3};"
                 : "+f"(d[0]), "+f"(d[1]), "+f"(d[2]), "+f"(d[3])
                 : "r"(a[0]), "r"(a[1]), "r"(a[2]), "r"(a[3]), "r"(b[0]), "r"(b[1]));
}

// ---------------- Kernel 1: transpose x -> fp16, fused mean + halo + ctr reset ----------------
__global__ void __launch_bounds__(256) prepx_kernel(const float* __restrict__ x) {
    __shared__ float tile[CINC][33];
    __shared__ float s_red[256];
    int xh = blockIdx.x, x0 = xh * 32, y = blockIdx.y, b = blockIdx.z;
    int tid = threadIdx.x;
    if (b == 0 && y == 0 && xh == 0 && tid == 0) g_tilectr = 0;

    #pragma unroll
    for (int r = 0; r < 16; ++r) {
        int ci = r*8 + (tid >> 5), xp = tid & 31;
        tile[ci][xp] = x[(((size_t)b*CINC + ci)*HH + y)*WW + x0 + xp];
    }
    __syncthreads();
    int ci = tid & 127;
    float s = 0.f;
    #pragma unroll
    for (int r = 0; r < 16; ++r) {
        int xp = r*2 + (tid >> 7);
        float v = tile[ci][xp];
        s += v;
        size_t off = (((size_t)b*HP + (y+1))*HP + (x0 + xp + 1))*CINC + ci;
        g_x[off] = __float2half(v);
    }
    s_red[tid] = s;

    // halo zeroing (no extra kernel)
    const __half hz = __float2half(0.f);
    if (y == 0 || y == HH-1) {
        int yy = (y == 0) ? 0 : HP-1;
        for (int i = tid; i < 33*CINC; i += 256) {
            int site = xh*33 + (i >> 7);
            g_x[(((size_t)b*HP + yy)*HP + site)*CINC + (i & 127)] = hz;
        }
    }
    if (tid < 128) {
        int xx = xh ? HP-1 : 0;
        g_x[(((size_t)b*HP + (y+1))*HP + xx)*CINC + tid] = hz;
    }

    __syncthreads();
    if (tid < 128)
        g_part[((size_t)b*CINC + tid)*128 + y*2 + xh] = s_red[tid] + s_red[tid + 128];
}

// ---------------- Kernel 2: attention MLP + softmax + agg bias ----------------
__global__ void __launch_bounds__(128) att_kernel(const float* __restrict__ fc1_w,
                                                  const float* __restrict__ fc2_w,
                                                  const float* __restrict__ fc2_b,
                                                  const float* __restrict__ bias) {
    const int b = blockIdx.x;
    const int tid = threadIdx.x, wid = tid >> 5, lane = tid & 31;
    __shared__ float s_ctx[CINC];
    __shared__ float s_hid[HIDN];
    __shared__ float s_att[NK];

    {
        const float* pp = g_part + ((size_t)b*CINC + tid)*128;
        float s = 0.f;
        #pragma unroll 8
        for (int j = 0; j < 128; ++j) s += pp[j];
        s_ctx[tid] = s * (1.0f / (HH*WW));
    }
    __syncthreads();

    #pragma unroll
    for (int i = 0; i < 8; ++i) {
        int h = wid*8 + i;
        float s = 0.f;
        #pragma unroll
        for (int j = 0; j < 4; ++j) {
            int c = lane + j*32;
            s += s_ctx[c] * fc1_w[h*CINC + c];
        }
        #pragma unroll
        for (int o = 16; o > 0; o >>= 1) s += __shfl_xor_sync(0xffffffffu, s, o);
        if (lane == 0) s_hid[h] = fmaxf(s, 0.f);
    }
    __syncthreads();

    if (wid == 0) {
        int k = lane >> 3, l8 = lane & 7;
        float s = 0.f;
        #pragma unroll
        for (int j = 0; j < 4; ++j) {
            int h = l8 + j*8;
            s += s_hid[h] * fc2_w[k*HIDN + h];
        }
        #pragma unroll
        for (int o = 4; o > 0; o >>= 1) s += __shfl_xor_sync(0xffffffffu, s, o);
        s += fc2_b[k];
        float lg = s * (1.0f / TEMPF);
        float m = lg;
        #pragma unroll
        for (int o = 16; o >= 8; o >>= 1) m = fmaxf(m, __shfl_xor_sync(0xffffffffu, m, o));
        float e = expf(lg - m);
        float sum = e;
        #pragma unroll
        for (int o = 16; o >= 8; o >>= 1) sum += __shfl_xor_sync(0xffffffffu, sum, o);
        if (l8 == 0) {
            float a = e / sum;
            s_att[k] = a;
            g_att[b*NK + k] = a;
        }
    }
    __syncthreads();

    float sb = 0.f;
    #pragma unroll
    for (int k = 0; k < NK; ++k) sb += s_att[k] * bias[k*COUTC + tid];
    g_aggb[b*COUTC + tid] = sb;
}

// ---------------- Kernel 3: aggregate weights -> fp16 (coalesced + smem transpose) ----------------
__global__ void __launch_bounds__(256) prepw_kernel(const float* __restrict__ weight) {
    __shared__ float s_w[NK][9*CINC];     // 18 KB
    __shared__ float s_agg[9*CINC];       // 4.5 KB
    int co = blockIdx.x, b = blockIdx.y;
    int tid = threadIdx.x;
    // coalesced load: for each k, the (ci,t) block for this co is 1152 contiguous floats
    for (int idx = tid; idx < NK*9*CINC; idx += 256) {
        int k = idx / (9*CINC), j = idx % (9*CINC);
        s_w[k][j] = weight[(size_t)(k*COUTC + co)*(9*CINC) + j];
    }
    float a[NK];
    #pragma unroll
    for (int k = 0; k < NK; ++k) a[k] = g_att[b*NK + k];
    __syncthreads();
    for (int j = tid; j < 9*CINC; j += 256) {
        float s = 0.f;
        #pragma unroll
        for (int k = 0; k < NK; ++k) s += a[k] * s_w[k][j];
        s_agg[j] = s;
    }
    __syncthreads();
    // coalesced store: [t][co][ci], ci contiguous
    for (int idx = tid; idx < 9*CINC; idx += 256) {
        int t = idx >> 7, ci = idx & 127;
        g_w[(((size_t)(b*9 + t)*COUTC) + co)*CINC + ci] = __float2half(s_agg[ci*9 + t]);
    }
}

// ---------------- Kernel 4: persistent HMMA fp16 conv GEMM ----------------
// Tile: M=128 pixels (2 rows x 64), N=128 couts, 18 stages of K=64 (tap x ci-half).
// A: 4x66-line window, DOUBLE-buffered per ci-half (A1 prefetched with stage 6).
// B: 16KB/stage, double-buffered. ONE __syncthreads per stage.
// 304 persistent CTAs pull tiles off g_tilectr.
#define A_LINES 264
#define A_SP    (A_LINES*128)          // 33792
#define B_OFF   (2*A_SP)               // 67584
#define B_SUB   16384
#define SMEM_TOTAL (B_OFF + 2*B_SUB)   // 100352
#define NTILES  1024

__global__ void __launch_bounds__(256, 2) conv_kernel(float* __restrict__ out) {
    extern __shared__ __align__(1024) char smem[];
    __shared__ unsigned s_tile;
    const uint32_t sbase = smem_u32(smem);
    const int tid = threadIdx.x, wid = tid >> 5, lane = tid & 31;

    const int warp_m = wid >> 1;
    const int warp_n = wid & 1;

    const int quad = lane >> 3, l7 = lane & 7;
    const int a_row_off = ((quad & 1) << 3) + l7;
    const int a_k_off   = (quad >> 1) << 4;
    const int b_row_off = ((quad >> 1) << 3) + l7;
    const int b_k_off   = (quad & 1) << 4;

    for (;;) {
        if (tid == 0) s_tile = atomicAdd(&g_tilectr, 1u);
        __syncthreads();
        const unsigned t = s_tile;
        __syncthreads();
        if (t >= NTILES) break;
        const int b  = t & 31;
        const int y0 = (int)(t >> 5) * 2;

        float acc[2][8][4];
        #pragma unroll
        for (int mi = 0; mi < 2; ++mi)
            #pragma unroll
            for (int nf = 0; nf < 8; ++nf)
                #pragma unroll
                for (int e = 0; e < 4; ++e) acc[mi][nf][e] = 0.f;

        // stage A window for ci-half c2 into buffer abuf (2112 cp16)
        auto issue_A = [&](int abuf, int c2) {
            for (int idx = tid; idx < A_LINES*8; idx += 256) {
                int line = idx >> 3;
                int c8   = idx & 7;
                int r4   = line / 66;
                int c66  = line - r4*66;
                size_t e = (((size_t)b*HP + y0 + r4)*HP + c66)*CINC + c2*64;
                const char* src = (const char*)g_x + e*2 + c8*16;
                uint32_t dst = sbase + abuf*A_SP + line*128 + ((c8*16) ^ ((line & 7) << 4));
                cp16(dst, src);
            }
        };
        // stage B tile (1024 cp16): row = co, 128B = 64 ci fp16
        auto issue_B = [&](int bbuf, int g) {
            const int tap = g % 9, c2 = g / 9;
            #pragma unroll
            for (int i = 0; i < 4; ++i) {
                int idx = tid + i*256;
                int r  = idx >> 3;
                int c8 = idx & 7;
                size_t e = (((size_t)(b*9 + tap))*COUTC + r)*CINC + c2*64;
                const char* src = (const char*)g_w + e*2 + c8*16;
                uint32_t dst = sbase + B_OFF + bbuf*B_SUB + SW128(r*128 + c8*16);
                cp16(dst, src);
            }
        };

        issue_A(0, 0);
        issue_B(0, 0);
        CP_COMMIT();

        for (int g = 0; g < 18; ++g) {
            CP_WAIT0();
            __syncthreads();     // stage g visible everywhere; compute g-1 done everywhere
            if (g + 1 < 18) {
                issue_B((g + 1) & 1, g + 1);
                if (g == 5) issue_A(1, 1);   // A1 prefetch, merged into stage-6 group
                CP_COMMIT();
            }

            const int tap = g % 9;
            const int dy = tap / 3, dx = tap % 3;
            const uint32_t a_base = sbase + (g < 9 ? 0 : A_SP);
            const uint32_t b_base = sbase + B_OFF + (g & 1) * B_SUB;

            #pragma unroll
            for (int kc = 0; kc < 4; ++kc) {
                const int kb = kc * 32;
                uint32_t Am[2][4], Bm[4][4];
                #pragma unroll
                for (int mi = 0; mi < 2; ++mi) {
                    int p = warp_m*32 + mi*16 + a_row_off;
                    int line = ((p >> 6) + dy)*66 + (p & 63) + dx;
                    uint32_t off = line*128 + ((kb + a_k_off) ^ ((line & 7) << 4));
                    ldmx4(Am[mi], a_base + off);
                }
                #pragma unroll
                for (int nj = 0; nj < 4; ++nj) {
                    int row = warp_n*64 + nj*16 + b_row_off;
                    ldmx4(Bm[nj], b_base + SW128(row*128 + kb + b_k_off));
                }
                #pragma unroll
                for (int mi = 0; mi < 2; ++mi)
                    #pragma unroll
                    for (int nf = 0; nf < 8; ++nf) {
                        const uint32_t* bm = &Bm[nf >> 1][(nf & 1) * 2];
                        mma_f16(acc[mi][nf], Am[mi], bm);
                    }
            }
        }

        // ---- epilogue: regs -> smem [co][p] (overlays A0+A1) -> coalesced gmem + bias
        __syncthreads();
        float* stage = (float*)smem;            // [128][132] = 67584 B
        #pragma unroll
        for (int mi = 0; mi < 2; ++mi)
            #pragma unroll
            for (int nf = 0; nf < 8; ++nf)
                #pragma unroll
                for (int e = 0; e < 4; ++e) {
                    int p  = warp_m*32 + mi*16 + (lane >> 2) + ((e >> 1) << 3);
                    int co = warp_n*64 + nf*8 + ((lane & 3) << 1) + (e & 1);
                    stage[co*132 + p] = acc[mi][nf][e];
                }
        __syncthreads();
        #pragma unroll
        for (int i = 0; i < 16; ++i) {
            int idx = tid + i*256;               // 4096 quads
            int co = idx >> 5, pq = idx & 31;
            int p = pq * 4;
            float bb = g_aggb[b*COUTC + co];
            const float* sp = stage + co*132 + p;
            float4 v;
            v.x = sp[0] + bb; v.y = sp[1] + bb; v.z = sp[2] + bb; v.w = sp[3] + bb;
            *(float4*)(out + (((size_t)b*COUTC + co)*HH + y0 + (p >> 6))*WW + (p & 63)) = v;
        }
        __syncthreads();        // stage reads done before next tile's issue_A overwrites
    }
}

extern "C" void kernel_launch(void* const* d_in, const int* in_sizes, int n_in,
                              void* d_out, int out_size) {
    const float* x      = (const float*)d_in[0];
    const float* fc1_w  = (const float*)d_in[1];
    const float* fc2_w  = (const float*)d_in[2];
    const float* fc2_b  = (const float*)d_in[3];
    const float* weight = (const float*)d_in[4];
    const float* bias   = (const float*)d_in[5];
    float* out = (float*)d_out;

    cudaFuncSetAttribute(conv_kernel,
                         cudaFuncAttributeMaxDynamicSharedMemorySize, SMEM_TOTAL);

    prepx_kernel<<<dim3(2, HH, BB), 256>>>(x);
    att_kernel<<<BB, 128>>>(fc1_w, fc2_w, fc2_b, bias);
    prepw_kernel<<<dim3(COUTC, BB), 256>>>(weight);
    conv_kernel<<<304, 256, SMEM_TOTAL>>>(out);
}

// round 15
// speedup vs baseline: 1.0465x; 1.0465x over previous
#include <cuda_runtime.h>
#include <cuda_fp16.h>
#include <math.h>
#include <stdint.h>

#define BB    32
#define CINC  128
#define HH    64
#define WW    64
#define COUTC 128
#define NK    4
#define HIDN  32
#define TEMPF 34.0f

// halo-padded channel-last input: [B][66][66][CIN] fp16
#define HP 66
__device__ __half g_x[(size_t)BB*HP*HP*CINC];
// aggregated weights: [B][9][COUT][CIN] fp16
__device__ __half g_w[(size_t)BB*9*COUTC*CINC];
__device__ float g_part[(size_t)BB*CINC*128];   // mean partials: [b][ci][y*2+xhalf]
__device__ float g_att[BB*NK];
__device__ float g_aggb[BB*COUTC];

// ---------------- PTX helpers ----------------
__device__ __forceinline__ uint32_t smem_u32(const void* p) {
    uint32_t a;
    asm("{ .reg .u64 t; cvta.to.shared.u64 t, %1; cvt.u32.u64 %0, t; }" : "=r"(a) : "l"(p));
    return a;
}
#define SW128(off) ((off) ^ (((off) >> 3) & 0x70))

__device__ __forceinline__ void cp16(uint32_t dst, const void* src) {
    asm volatile("cp.async.cg.shared.global [%0], [%1], 16;" :: "r"(dst), "l"(src));
}
#define CP_COMMIT() asm volatile("cp.async.commit_group;" ::: "memory")
#define CP_WAIT1()  asm volatile("cp.async.wait_group 1;" ::: "memory")
#define CP_WAIT0()  asm volatile("cp.async.wait_group 0;" ::: "memory")

__device__ __forceinline__ void ldmx4(uint32_t* r, uint32_t addr) {
    asm volatile("ldmatrix.sync.aligned.m8n8.x4.shared.b16 {%0,%1,%2,%3}, [%4];"
                 : "=r"(r[0]), "=r"(r[1]), "=r"(r[2]), "=r"(r[3]) : "r"(addr));
}
__device__ __forceinline__ void mma_f16(float* d, const uint32_t* a, const uint32_t* b) {
    asm volatile("mma.sync.aligned.m16n8k16.row.col.f32.f16.f16.f32 "
                 "{%0,%1,%2,%3}, {%4,%5,%6,%7}, {%8,%9}, {%0,%1,%2,%3};"
                 : "+f"(d[0]), "+f"(d[1]), "+f"(d[2]), "+f"(d[3])
                 : "r"(a[0]), "r"(a[1]), "r"(a[2]), "r"(a[3]), "r"(b[0]), "r"(b[1]));
}

// ---------------- Kernel 1: transpose x -> fp16, fused mean + halo ----------------
__global__ void __launch_bounds__(256) prepx_kernel(const float* __restrict__ x) {
    __shared__ float tile[CINC][33];
    __shared__ float s_red[256];
    int xh = blockIdx.x, x0 = xh * 32, y = blockIdx.y, b = blockIdx.z;
    int tid = threadIdx.x;

    #pragma unroll
    for (int r = 0; r < 16; ++r) {
        int ci = r*8 + (tid >> 5), xp = tid & 31;
        tile[ci][xp] = x[(((size_t)b*CINC + ci)*HH + y)*WW + x0 + xp];
    }
    __syncthreads();
    int ci = tid & 127;
    float s = 0.f;
    #pragma unroll
    for (int r = 0; r < 16; ++r) {
        int xp = r*2 + (tid >> 7);
        float v = tile[ci][xp];
        s += v;
        size_t off = (((size_t)b*HP + (y+1))*HP + (x0 + xp + 1))*CINC + ci;
        g_x[off] = __float2half(v);
    }
    s_red[tid] = s;

    // halo zeroing (no extra kernel)
    const __half hz = __float2half(0.f);
    if (y == 0 || y == HH-1) {
        int yy = (y == 0) ? 0 : HP-1;
        for (int i = tid; i < 33*CINC; i += 256) {
            int site = xh*33 + (i >> 7);
            g_x[(((size_t)b*HP + yy)*HP + site)*CINC + (i & 127)] = hz;
        }
    }
    if (tid < 128) {
        int xx = xh ? HP-1 : 0;
        g_x[(((size_t)b*HP + (y+1))*HP + xx)*CINC + tid] = hz;
    }

    __syncthreads();
    if (tid < 128)
        g_part[((size_t)b*CINC + tid)*128 + y*2 + xh] = s_red[tid] + s_red[tid + 128];
}

// ---------------- Kernel 2: attention MLP + softmax + agg bias ----------------
__global__ void __launch_bounds__(128) att_kernel(const float* __restrict__ fc1_w,
                                                  const float* __restrict__ fc2_w,
                                                  const float* __restrict__ fc2_b,
                                                  const float* __restrict__ bias) {
    const int b = blockIdx.x;
    const int tid = threadIdx.x, wid = tid >> 5, lane = tid & 31;
    __shared__ float s_ctx[CINC];
    __shared__ float s_hid[HIDN];
    __shared__ float s_att[NK];

    {
        const float* pp = g_part + ((size_t)b*CINC + tid)*128;
        float s = 0.f;
        #pragma unroll 8
        for (int j = 0; j < 128; ++j) s += pp[j];
        s_ctx[tid] = s * (1.0f / (HH*WW));
    }
    __syncthreads();

    #pragma unroll
    for (int i = 0; i < 8; ++i) {
        int h = wid*8 + i;
        float s = 0.f;
        #pragma unroll
        for (int j = 0; j < 4; ++j) {
            int c = lane + j*32;
            s += s_ctx[c] * fc1_w[h*CINC + c];
        }
        #pragma unroll
        for (int o = 16; o > 0; o >>= 1) s += __shfl_xor_sync(0xffffffffu, s, o);
        if (lane == 0) s_hid[h] = fmaxf(s, 0.f);
    }
    __syncthreads();

    if (wid == 0) {
        int k = lane >> 3, l8 = lane & 7;
        float s = 0.f;
        #pragma unroll
        for (int j = 0; j < 4; ++j) {
            int h = l8 + j*8;
            s += s_hid[h] * fc2_w[k*HIDN + h];
        }
        #pragma unroll
        for (int o = 4; o > 0; o >>= 1) s += __shfl_xor_sync(0xffffffffu, s, o);
        s += fc2_b[k];
        float lg = s * (1.0f / TEMPF);
        float m = lg;
        #pragma unroll
        for (int o = 16; o >= 8; o >>= 1) m = fmaxf(m, __shfl_xor_sync(0xffffffffu, m, o));
        float e = expf(lg - m);
        float sum = e;
        #pragma unroll
        for (int o = 16; o >= 8; o >>= 1) sum += __shfl_xor_sync(0xffffffffu, sum, o);
        if (l8 == 0) {
            float a = e / sum;
            s_att[k] = a;
            g_att[b*NK + k] = a;
        }
    }
    __syncthreads();

    float sb = 0.f;
    #pragma unroll
    for (int k = 0; k < NK; ++k) sb += s_att[k] * bias[k*COUTC + tid];
    g_aggb[b*COUTC + tid] = sb;
}

// ---------------- Kernel 3: aggregate weights -> fp16 (coalesced + smem transpose) ----------------
__global__ void __launch_bounds__(256) prepw_kernel(const float* __restrict__ weight) {
    __shared__ float s_w[NK][9*CINC];     // 18 KB
    __shared__ float s_agg[9*CINC];       // 4.5 KB
    int co = blockIdx.x, b = blockIdx.y;
    int tid = threadIdx.x;
    for (int idx = tid; idx < NK*9*CINC; idx += 256) {
        int k = idx / (9*CINC), j = idx % (9*CINC);
        s_w[k][j] = weight[(size_t)(k*COUTC + co)*(9*CINC) + j];
    }
    float a[NK];
    #pragma unroll
    for (int k = 0; k < NK; ++k) a[k] = g_att[b*NK + k];
    __syncthreads();
    for (int j = tid; j < 9*CINC; j += 256) {
        float s = 0.f;
        #pragma unroll
        for (int k = 0; k < NK; ++k) s += a[k] * s_w[k][j];
        s_agg[j] = s;
    }
    __syncthreads();
    for (int idx = tid; idx < 9*CINC; idx += 256) {
        int t = idx >> 7, ci = idx & 127;
        g_w[(((size_t)(b*9 + t)*COUTC) + co)*CINC + ci] = __float2half(s_agg[ci*9 + t]);
    }
}

// ---------------- Kernel 4: HMMA fp16 single-product conv GEMM (R13 structure) ----------------
// CTA: M=128 pixels (2 rows x 64), N=128 couts. 18 stages of K=64 (tap x ci-half).
// A: padded window 4 rows x 66 cols x 64ci fp16 = 33792 B, single buffer,
//    reloaded once at the ci-half switch (pipelined behind B).
// B: stage = (tap, ci-half): 128co x 64ci x 2B = 16KB, x2 buffers.
#define A_LINES 264
#define A_SP    (A_LINES*128)          // 33792
#define B_SUB   16384
#define B_OFF   A_SP                   // 33792
#define SMEM_TOTAL 67584               // max(B_OFF + 2*B_SUB = 66560, epilogue 67584)

__global__ void __launch_bounds__(256, 2) conv_kernel(float* __restrict__ out) {
    extern __shared__ __align__(1024) char smem[];
    const uint32_t sbase = smem_u32(smem);
    const int tid = threadIdx.x, wid = tid >> 5, lane = tid & 31;
    const int b = blockIdx.y;
    const int y0 = blockIdx.x * 2;

    const int warp_m = wid >> 1;
    const int warp_n = wid & 1;

    const int quad = lane >> 3, l7 = lane & 7;
    const int a_row_off = ((quad & 1) << 3) + l7;
    const int a_k_off   = (quad >> 1) << 4;
    const int b_row_off = ((quad >> 1) << 3) + l7;
    const int b_k_off   = (quad & 1) << 4;

    float acc[2][8][4];
    #pragma unroll
    for (int mi = 0; mi < 2; ++mi)
        #pragma unroll
        for (int nf = 0; nf < 8; ++nf)
            #pragma unroll
            for (int e = 0; e < 4; ++e) acc[mi][nf][e] = 0.f;

    // stage A window for ci-half c2 (2112 cp16)
    auto issue_A = [&](int c2) {
        for (int idx = tid; idx < A_LINES*8; idx += 256) {
            int line = idx >> 3;
            int c8   = idx & 7;
            int r4   = line / 66;
            int c66  = line - r4*66;
            size_t e = (((size_t)b*HP + y0 + r4)*HP + c66)*CINC + c2*64;
            const char* src = (const char*)g_x + e*2 + c8*16;
            uint32_t dst = sbase + line*128 + ((c8*16) ^ ((line & 7) << 4));
            cp16(dst, src);
        }
    };
    // stage B tile (1024 cp16): row = co, 128B = 64 ci fp16
    auto issue_B = [&](int bbuf, int g) {
        const int tap = g % 9, c2 = g / 9;
        #pragma unroll
        for (int i = 0; i < 4; ++i) {
            int idx = tid + i*256;
            int r  = idx >> 3;
            int c8 = idx & 7;
            size_t e = (((size_t)(b*9 + tap))*COUTC + r)*CINC + c2*64;
            const char* src = (const char*)g_w + e*2 + c8*16;
            uint32_t dst = sbase + B_OFF + bbuf*B_SUB + SW128(r*128 + c8*16);
            cp16(dst, src);
        }
    };

    issue_A(0);
    CP_COMMIT();
    issue_B(0, 0);
    CP_COMMIT();

    for (int g = 0; g < 18; ++g) {
        __syncthreads();                        // prior compute done before overwrite
        if (g == 9) { issue_A(1); CP_COMMIT(); }     // ci-half switch: reload A
        if (g + 1 < 18) {
            issue_B((g + 1) & 1, g + 1);
            CP_COMMIT();
            CP_WAIT1();
        } else {
            CP_WAIT0();
        }
        __syncthreads();

        const int tap = g % 9;
        const int dy = tap / 3, dx = tap % 3;
        const uint32_t b_base = sbase + B_OFF + (g & 1) * B_SUB;

        #pragma unroll
        for (int kc = 0; kc < 4; ++kc) {
            const int kb = kc * 32;
            uint32_t Am[2][4], Bm[4][4];
            #pragma unroll
            for (int mi = 0; mi < 2; ++mi) {
                int p = warp_m*32 + mi*16 + a_row_off;
                int line = ((p >> 6) + dy)*66 + (p & 63) + dx;
                uint32_t off = line*128 + ((kb + a_k_off) ^ ((line & 7) << 4));
                ldmx4(Am[mi], sbase + off);
            }
            #pragma unroll
            for (int nj = 0; nj < 4; ++nj) {
                int row = warp_n*64 + nj*16 + b_row_off;
                ldmx4(Bm[nj], b_base + SW128(row*128 + kb + b_k_off));
            }
            #pragma unroll
            for (int mi = 0; mi < 2; ++mi)
                #pragma unroll
                for (int nf = 0; nf < 8; ++nf) {
                    const uint32_t* bm = &Bm[nf >> 1][(nf & 1) * 2];
                    mma_f16(acc[mi][nf], Am[mi], bm);
                }
        }
    }

    // ---- epilogue: regs -> smem [co][p] -> coalesced gmem + bias
    __syncthreads();
    float* stage = (float*)smem;            // [128][132] = 67584 B
    #pragma unroll
    for (int mi = 0; mi < 2; ++mi)
        #pragma unroll
        for (int nf = 0; nf < 8; ++nf)
            #pragma unroll
            for (int e = 0; e < 4; ++e) {
                int p  = warp_m*32 + mi*16 + (lane >> 2) + ((e >> 1) << 3);
                int co = warp_n*64 + nf*8 + ((lane & 3) << 1) + (e & 1);
                stage[co*132 + p] = acc[mi][nf][e];
            }
    __syncthreads();
    #pragma unroll
    for (int i = 0; i < 16; ++i) {
        int idx = tid + i*256;               // 4096 quads
        int co = idx >> 5, pq = idx & 31;
        int p = pq * 4;
        float bb = g_aggb[b*COUTC + co];
        const float* sp = stage + co*132 + p;
        float4 v;
        v.x = sp[0] + bb; v.y = sp[1] + bb; v.z = sp[2] + bb; v.w = sp[3] + bb;
        *(float4*)(out + (((size_t)b*COUTC + co)*HH + y0 + (p >> 6))*WW + (p & 63)) = v;
    }
}

extern "C" void kernel_launch(void* const* d_in, const int* in_sizes, int n_in,
                              void* d_out, int out_size) {
    const float* x      = (const float*)d_in[0];
    const float* fc1_w  = (const float*)d_in[1];
    const float* fc2_w  = (const float*)d_in[2];
    const float* fc2_b  = (const float*)d_in[3];
    const float* weight = (const float*)d_in[4];
    const float* bias   = (const float*)d_in[5];
    float* out = (float*)d_out;

    cudaFuncSetAttribute(conv_kernel,
                         cudaFuncAttributeMaxDynamicSharedMemorySize, SMEM_TOTAL);

    prepx_kernel<<<dim3(2, HH, BB), 256>>>(x);
    att_kernel<<<BB, 128>>>(fc1_w, fc2_w, fc2_b, bias);
    prepw_kernel<<<dim3(COUTC, BB), 256>>>(weight);
    conv_kernel<<<dim3(HH/2, BB), 256, SMEM_TOTAL>>>(out);
}